// round 9
// baseline (speedup 1.0000x reference)
#include <cuda_runtime.h>
#include <cuda_fp16.h>

#define NB   8
#define TOUT 256
#define TIN  512
#define LH   128
#define G4   512
#define DIN  128
#define DATT 128

#define OUT_X_ELEMS (NB*TOUT*(LH+DATT))
#define OUT_H_OFF   (OUT_X_ELEMS)
#define OUT_C_OFF   (OUT_X_ELEMS + NB*LH)

// ---- LSTM config (f32x2 packed) ----
#define KREGR 64                          // k-rows in registers (32 f32x2 pairs)
#define WST4  17                          // smem row stride in ulonglong2 (16 data + 1 pad)
#define LSTM_DSMEM (512 * WST4 * 16)      // 139264 B

// ---- score config (R6, proven) ----
#define KPW  68                           // key row stride in half2 words
#define KP4  17                           // ... in uint4
#define S_KEYS_SZ (128 * KPW * 4)         // 34816
#define S_Q_SZ    (8 * 64 * 4)            // 2048
#define S_W3_SZ   (64 * 4)                // 256
#define SCORE_DSMEM (S_KEYS_SZ + S_Q_SZ + S_W3_SZ)   // 37120

__device__ float  g_xz[NB*TOUT*G4];
__device__ __half g_keys_h[NB*TIN*LH];
__device__ __half g_q_h[NB*TOUT*LH];
__device__ float  g_sc[NB*TOUT*TIN];

// ---- helpers ----
__device__ __forceinline__ float ex2f(float x) {
    float y; asm("ex2.approx.f32 %0, %1;" : "=f"(y) : "f"(x)); return y;
}
__device__ __forceinline__ float rcpf(float x) {
    float y; asm("rcp.approx.f32 %0, %1;" : "=f"(y) : "f"(x)); return y;
}
__device__ __forceinline__ float tanh_fast(float x) {
    float t = ex2f(x * 2.885390082f);
    return fmaf(-2.0f, rcpf(1.0f + t), 1.0f);
}
__device__ __forceinline__ float sigm_fast(float x) {
    float t = ex2f(x * -1.442695041f);
    return rcpf(1.0f + t);
}
__device__ __forceinline__ unsigned tanh_u2(unsigned x) {
    unsigned r;
    asm("tanh.approx.f16x2 %0, %1;" : "=r"(r) : "r"(x));
    return r;
}
__device__ __forceinline__ __half2 u2h2(unsigned u) {
    __half2 h; *reinterpret_cast<unsigned*>(&h) = u; return h;
}
__device__ __forceinline__ unsigned hadd2u(unsigned a, unsigned b) {
    __half2 r = __hadd2(u2h2(a), u2h2(b));
    return *reinterpret_cast<unsigned*>(&r);
}
// packed f32x2 (Blackwell): d += a * b elementwise on packed pairs
__device__ __forceinline__ void fma2(unsigned long long& d,
                                     unsigned long long a, unsigned long long b) {
    asm("fma.rn.f32x2 %0, %1, %2, %0;" : "+l"(d) : "l"(a), "l"(b));
}
__device__ __forceinline__ unsigned long long packf2(float lo, float hi) {
    unsigned long long r;
    asm("mov.b64 %0, {%1, %2};" : "=l"(r) : "f"(lo), "f"(hi));
    return r;
}
__device__ __forceinline__ float2 unpackf2(unsigned long long u) {
    float2 f;
    asm("mov.b64 {%0, %1}, %2;" : "=f"(f.x), "=f"(f.y) : "l"(u));
    return f;
}

// ---------------------------------------------------------------------------
// K1: fused projections, tiled. keys emitted in half.
// ---------------------------------------------------------------------------
__global__ void __launch_bounds__(128) proj_kernel(
    const float* __restrict__ att, const float* __restrict__ W1,
    const float* __restrict__ b1,  __half* __restrict__ keys_h,
    const float* __restrict__ inp, const float* __restrict__ Wk,
    const float* __restrict__ lbias, float* __restrict__ xz)
{
    int bid = blockIdx.x;
    int j = threadIdx.x;
    if (bid < 256) {
        __shared__ float a_s[16][DATT];
        int row0 = bid * 16;
        for (int i = j; i < 16 * DATT; i += 128) {
            int r = i >> 7, d = i & 127;
            a_s[r][d] = att[(row0 + r) * DATT + d];
        }
        __syncthreads();
        float acc[16];
        float bj = b1[j];
        #pragma unroll
        for (int r = 0; r < 16; r++) acc[r] = bj;
        for (int l = 0; l < DATT; l++) {
            float wl = W1[l * LH + j];
            #pragma unroll
            for (int r = 0; r < 16; r++)
                acc[r] += a_s[r][l] * wl;
        }
        #pragma unroll
        for (int r = 0; r < 16; r++)
            keys_h[(row0 + r) * LH + j] = __float2half(acc[r]);
    } else {
        __shared__ float a_s[8][DIN];
        int row0 = (bid - 256) * 8;
        for (int i = j; i < 8 * DIN; i += 128) {
            int r = i >> 7, d = i & 127;
            a_s[r][d] = inp[(row0 + r) * DIN + d];
        }
        __syncthreads();
        float acc[4][8];
        #pragma unroll
        for (int c = 0; c < 4; c++) {
            float bc = lbias[j + c * 128];
            #pragma unroll
            for (int r = 0; r < 8; r++) acc[c][r] = bc;
        }
        for (int d = 0; d < DIN; d++) {
            float w0 = Wk[d * G4 + j];
            float w1 = Wk[d * G4 + j + 128];
            float w2 = Wk[d * G4 + j + 256];
            float w3 = Wk[d * G4 + j + 384];
            #pragma unroll
            for (int r = 0; r < 8; r++) {
                float av = a_s[r][d];
                acc[0][r] += av * w0;
                acc[1][r] += av * w1;
                acc[2][r] += av * w2;
                acc[3][r] += av * w3;
            }
        }
        #pragma unroll
        for (int r = 0; r < 8; r++) {
            float* o = xz + (row0 + r) * G4;
            o[j] = acc[0][r]; o[j + 128] = acc[1][r];
            o[j + 256] = acc[2][r]; o[j + 384] = acc[3][r];
        }
    }
}

// ---------------------------------------------------------------------------
// K2: LSTM scan — packed f32x2 FMA. Rows 0..63 in regs (32 pairs),
//     rows 64..127 packed in smem (conflict-free LDS.128). Full fp32.
// ---------------------------------------------------------------------------
__global__ void __launch_bounds__(512, 1) lstm_kernel(
    const float* __restrict__ xz, const float* __restrict__ Wr,
    float* __restrict__ out)
{
    int b = blockIdx.x;
    int j = threadIdx.x;
    __shared__ __align__(16) float h_s[LH];
    __shared__ float z_s[G4];
    extern __shared__ ulonglong2 w_s2[];      // [512][WST4]

    // pack smem weights: k-rows 64..127 -> 16 ulonglong2 per thread-column
    #pragma unroll 4
    for (int c = 0; c < 16; c++) {
        float w0 = Wr[(KREGR + 4 * c + 0) * G4 + j];
        float w1 = Wr[(KREGR + 4 * c + 1) * G4 + j];
        float w2 = Wr[(KREGR + 4 * c + 2) * G4 + j];
        float w3 = Wr[(KREGR + 4 * c + 3) * G4 + j];
        ulonglong2 v;
        v.x = packf2(w0, w1);
        v.y = packf2(w2, w3);
        w_s2[j * WST4 + c] = v;
    }
    // register weights: k-rows 0..63 -> 32 packed pairs
    unsigned long long wr2[32];
    #pragma unroll
    for (int p = 0; p < 32; p++)
        wr2[p] = packf2(Wr[(2 * p) * G4 + j], Wr[(2 * p + 1) * G4 + j]);

    if (j < LH) h_s[j] = 0.0f;
    float c = 0.0f;
    __syncthreads();

    const float* xzb = xz + b * TOUT * G4;
    float xnext = xzb[j];
    bool is_g = (j >= 2 * LH) && (j < 3 * LH);
    const ulonglong2* wrow = w_s2 + j * WST4;

    for (int t = 0; t < TOUT; t++) {
        float xv = xnext;
        if (t + 1 < TOUT) xnext = xzb[(t + 1) * G4 + j];

        unsigned long long a0 = 0, a1 = 0, a2 = 0, a3 = 0;
        #pragma unroll
        for (int cc = 0; cc < 16; cc++) {
            ulonglong2 hv = *reinterpret_cast<const ulonglong2*>(&h_s[4 * cc]);
            fma2(a0, hv.x, wr2[2 * cc]);
            fma2(a1, hv.y, wr2[2 * cc + 1]);
        }
        #pragma unroll
        for (int cc = 0; cc < 16; cc++) {
            ulonglong2 hv = *reinterpret_cast<const ulonglong2*>(&h_s[64 + 4 * cc]);
            ulonglong2 wv = wrow[cc];
            fma2(a2, hv.x, wv.x);
            fma2(a3, hv.y, wv.y);
        }
        float2 f0 = unpackf2(a0), f1 = unpackf2(a1);
        float2 f2 = unpackf2(a2), f3 = unpackf2(a3);
        float z = xv + ((f0.x + f0.y) + (f1.x + f1.y))
                     + ((f2.x + f2.y) + (f3.x + f3.y));
        z_s[j] = is_g ? tanh_fast(z) : sigm_fast(z);
        __syncthreads();
        if (j < LH) {
            c = z_s[LH + j] * c + z_s[j] * z_s[2 * LH + j];
            float h = z_s[3 * LH + j] * tanh_fast(c);
            h_s[j] = h;
            out[(b * TOUT + t) * (LH + DATT) + j] = h;
        }
        __syncthreads();
    }
    if (j < LH) {
        out[OUT_H_OFF + b * LH + j] = h_s[j];
        out[OUT_C_OFF + b * LH + j] = c;
    }
}

// ---------------------------------------------------------------------------
// K3: q = x @ W2 + b2 -> half, tiled.
// ---------------------------------------------------------------------------
__global__ void __launch_bounds__(128) q_kernel(
    const float* __restrict__ out, const float* __restrict__ W2,
    const float* __restrict__ b2, __half* __restrict__ q_h)
{
    int row0 = blockIdx.x * 16;
    int j = threadIdx.x;
    __shared__ float x_s[16][LH];
    for (int i = j; i < 16 * LH; i += 128) {
        int r = i >> 7, l = i & 127;
        x_s[r][l] = out[(row0 + r) * (LH + DATT) + l];
    }
    __syncthreads();
    float acc[16];
    float bj = b2[j];
    #pragma unroll
    for (int r = 0; r < 16; r++) acc[r] = bj;
    for (int l = 0; l < LH; l++) {
        float wl = W2[l * LH + j];
        #pragma unroll
        for (int r = 0; r < 16; r++)
            acc[r] += x_s[r][l] * wl;
    }
    #pragma unroll
    for (int r = 0; r < 16; r++)
        q_h[(row0 + r) * LH + j] = __float2half(acc[r]);
}

// ---------------------------------------------------------------------------
// K4: raw scores (R6, proven best: f16x2 tanh, 4 key chains, 256 thr).
// ---------------------------------------------------------------------------
__global__ void __launch_bounds__(256, 4) score_kernel(
    const __half* __restrict__ keys_h_g, const __half* __restrict__ q_h_g,
    const float* __restrict__ W3, float* __restrict__ sc_g)
{
    extern __shared__ char sm[];
    uint4*    keyv = reinterpret_cast<uint4*>(sm);                  // [128][KP4]
    uint4*    qv   = reinterpret_cast<uint4*>(sm + S_KEYS_SZ);      // [8][16]
    uint4*    w3v  = reinterpret_cast<uint4*>(sm + S_KEYS_SZ + S_Q_SZ); // [16]
    unsigned* w3w  = reinterpret_cast<unsigned*>(sm + S_KEYS_SZ + S_Q_SZ);

    int b  = blockIdx.z;
    int q0 = blockIdx.y * 8;
    int k0 = blockIdx.x * 128;
    int tid = threadIdx.x;

    const uint4* kg = reinterpret_cast<const uint4*>(keys_h_g + (b * TIN + k0) * LH);
    for (int i = tid; i < 128 * 16; i += 256) {
        int k = i >> 4, cc = i & 15;
        keyv[k * KP4 + cc] = kg[k * 16 + cc];
    }
    if (tid < 128) {
        int r = tid >> 4, cc = tid & 15;
        qv[r * 16 + cc] = reinterpret_cast<const uint4*>(
            q_h_g + (b * TOUT + q0 + r) * LH)[cc];
    }
    if (tid < 64) {
        float2 v = *reinterpret_cast<const float2*>(&W3[2 * tid]);
        __half2 h = __floats2half2_rn(v.x, v.y);
        w3w[tid] = *reinterpret_cast<unsigned*>(&h);
    }
    __syncthreads();

    int ql = tid >> 5;
    int kk = tid & 31;
    const uint4* qrow = qv + ql * 16;

    float f0 = 0.f, f1 = 0.f, f2 = 0.f, f3 = 0.f;
    #pragma unroll
    for (int g2 = 0; g2 < 8; g2++) {
        __half2 z = __floats2half2_rn(0.f, 0.f);
        __half2 a0 = z, a1 = z, a2 = z, a3 = z;
        #pragma unroll
        for (int gg = 0; gg < 2; gg++) {
            int g = g2 * 2 + gg;
            uint4 q4 = qrow[g];
            uint4 w4 = w3v[g];
            uint4 kA = keyv[kk * KP4 + g];
            uint4 kB = keyv[(kk + 32) * KP4 + g];
            uint4 kC = keyv[(kk + 64) * KP4 + g];
            uint4 kD = keyv[(kk + 96) * KP4 + g];
            a0 = __hfma2(u2h2(tanh_u2(hadd2u(kA.x, q4.x))), u2h2(w4.x), a0);
            a1 = __hfma2(u2h2(tanh_u2(hadd2u(kB.x, q4.x))), u2h2(w4.x), a1);
            a2 = __hfma2(u2h2(tanh_u2(hadd2u(kC.x, q4.x))), u2h2(w4.x), a2);
            a3 = __hfma2(u2h2(tanh_u2(hadd2u(kD.x, q4.x))), u2h2(w4.x), a3);
            a0 = __hfma2(u2h2(tanh_u2(hadd2u(kA.y, q4.y))), u2h2(w4.y), a0);
            a1 = __hfma2(u2h2(tanh_u2(hadd2u(kB.y, q4.y))), u2h2(w4.y), a1);
            a2 = __hfma2(u2h2(tanh_u2(hadd2u(kC.y, q4.y))), u2h2(w4.y), a2);
            a3 = __hfma2(u2h2(tanh_u2(hadd2u(kD.y, q4.y))), u2h2(w4.y), a3);
            a0 = __hfma2(u2h2(tanh_u2(hadd2u(kA.z, q4.z))), u2h2(w4.z), a0);
            a1 = __hfma2(u2h2(tanh_u2(hadd2u(kB.z, q4.z))), u2h2(w4.z), a1);
            a2 = __hfma2(u2h2(tanh_u2(hadd2u(kC.z, q4.z))), u2h2(w4.z), a2);
            a3 = __hfma2(u2h2(tanh_u2(hadd2u(kD.z, q4.z))), u2h2(w4.z), a3);
            a0 = __hfma2(u2h2(tanh_u2(hadd2u(kA.w, q4.w))), u2h2(w4.w), a0);
            a1 = __hfma2(u2h2(tanh_u2(hadd2u(kB.w, q4.w))), u2h2(w4.w), a1);
            a2 = __hfma2(u2h2(tanh_u2(hadd2u(kC.w, q4.w))), u2h2(w4.w), a2);
            a3 = __hfma2(u2h2(tanh_u2(hadd2u(kD.w, q4.w))), u2h2(w4.w), a3);
        }
        float2 t0 = __half22float2(a0); f0 += t0.x + t0.y;
        float2 t1 = __half22float2(a1); f1 += t1.x + t1.y;
        float2 t2 = __half22float2(a2); f2 += t2.x + t2.y;
        float2 t3 = __half22float2(a3); f3 += t3.x + t3.y;
    }
    float* orow = sc_g + (b * TOUT + q0 + ql) * TIN + k0;
    orow[kk]      = f0;
    orow[kk + 32] = f1;
    orow[kk + 64] = f2;
    orow[kk + 96] = f3;
}

// ---------------------------------------------------------------------------
// K5: fused softmax + weighted.
// ---------------------------------------------------------------------------
__global__ void __launch_bounds__(256) weighted_kernel(
    const float* __restrict__ sc_g, const float* __restrict__ att,
    float* __restrict__ out)
{
    int b  = blockIdx.y;
    int q0 = blockIdx.x * 16;
    int tid = threadIdx.x;

    __shared__ float a_s[16][TIN];
    for (int i = tid; i < 16 * TIN; i += 256) {
        int r = i >> 9, kk = i & 511;
        a_s[r][kk] = sc_g[(b * TOUT + q0 + r) * TIN + kk];
    }
    __syncthreads();

    int w = tid >> 5, lane = tid & 31;
    for (int r = w; r < 16; r += 8) {
        float* row = a_s[r];
        float v[16], mx = -1e30f;
        #pragma unroll
        for (int i = 0; i < 16; i++) {
            v[i] = row[lane + 32 * i];
            mx = fmaxf(mx, v[i]);
        }
        #pragma unroll
        for (int off = 16; off >= 1; off >>= 1)
            mx = fmaxf(mx, __shfl_xor_sync(0xffffffffu, mx, off));
        float s = 0.0f;
        #pragma unroll
        for (int i = 0; i < 16; i++) {
            v[i] = ex2f((v[i] - mx) * 1.442695041f);
            s += v[i];
        }
        #pragma unroll
        for (int off = 16; off >= 1; off >>= 1)
            s += __shfl_xor_sync(0xffffffffu, s, off);
        float inv = rcpf(s);
        #pragma unroll
        for (int i = 0; i < 16; i++)
            row[lane + 32 * i] = v[i] * inv;
    }
    __syncthreads();

    int d = tid & 127;
    int g = tid >> 7;
    float acc[8];
    #pragma unroll
    for (int i = 0; i < 8; i++) acc[i] = 0.0f;

    const float* ap = att + b * TIN * DATT + d;
    #pragma unroll 4
    for (int k = 0; k < TIN; k++) {
        float av = ap[k * DATT];
        #pragma unroll
        for (int i = 0; i < 8; i++)
            acc[i] += a_s[g * 8 + i][k] * av;
    }
    #pragma unroll
    for (int i = 0; i < 8; i++)
        out[(b * TOUT + q0 + g * 8 + i) * (LH + DATT) + LH + d] = acc[i];
}

// ---------------------------------------------------------------------------
extern "C" void kernel_launch(void* const* d_in, const int* in_sizes, int n_in,
                              void* d_out, int out_size)
{
    const float* inputs   = (const float*)d_in[0];
    const float* attended = (const float*)d_in[1];
    const float* Wk       = (const float*)d_in[2];
    const float* Wr       = (const float*)d_in[3];
    const float* lbias    = (const float*)d_in[4];
    const float* W1       = (const float*)d_in[5];
    const float* b1       = (const float*)d_in[6];
    const float* W2       = (const float*)d_in[7];
    const float* b2       = (const float*)d_in[8];
    const float* W3       = (const float*)d_in[9];
    float* out = (float*)d_out;

    cudaFuncSetAttribute(lstm_kernel,
                         cudaFuncAttributeMaxDynamicSharedMemorySize, LSTM_DSMEM);
    cudaFuncSetAttribute(score_kernel,
                         cudaFuncAttributeMaxDynamicSharedMemorySize, SCORE_DSMEM);

    proj_kernel<<<512, 128>>>(attended, W1, b1, g_keys_h,
                              inputs, Wk, lbias, g_xz);
    lstm_kernel<<<NB, 512, LSTM_DSMEM>>>(g_xz, Wr, out);
    q_kernel<<<NB * TOUT / 16, 128>>>(out, W2, b2, g_q_h);
    {
        dim3 grid(TIN / 128, TOUT / 8, NB);
        score_kernel<<<grid, 256, SCORE_DSMEM>>>(g_keys_h, g_q_h, W3, g_sc);
    }
    {
        dim3 grid(16, NB);
        weighted_kernel<<<grid, 256>>>(g_sc, attended, out);
    }
    (void)in_sizes; (void)n_in; (void)out_size;
}

// round 10
// speedup vs baseline: 1.6566x; 1.6566x over previous
#include <cuda_runtime.h>
#include <cuda_fp16.h>

#define NB   8
#define TOUT 256
#define TIN  512
#define LH   128
#define G4   512
#define DIN  128
#define DATT 128

#define OUT_X_ELEMS (NB*TOUT*(LH+DATT))
#define OUT_H_OFF   (OUT_X_ELEMS)
#define OUT_C_OFF   (OUT_X_ELEMS + NB*LH)

// ---- LSTM config: all weights in registers ----
#define KF32 48                           // rows 0..47 as f32 regs
#define KH16 80                           // rows 48..127 as half2 regs (40 pairs)

// ---- score config (R6, proven) ----
#define KPW  68
#define KP4  17
#define S_KEYS_SZ (128 * KPW * 4)         // 34816
#define S_Q_SZ    (8 * 64 * 4)            // 2048
#define S_W3_SZ   (64 * 4)                // 256
#define SCORE_DSMEM (S_KEYS_SZ + S_Q_SZ + S_W3_SZ)   // 37120

__device__ float  g_xz[NB*TOUT*G4];
__device__ __half g_keys_h[NB*TIN*LH];
__device__ __half g_q_h[NB*TOUT*LH];
__device__ float  g_sc[NB*TOUT*TIN];

// ---- helpers ----
__device__ __forceinline__ float ex2f(float x) {
    float y; asm("ex2.approx.f32 %0, %1;" : "=f"(y) : "f"(x)); return y;
}
__device__ __forceinline__ float rcpf(float x) {
    float y; asm("rcp.approx.f32 %0, %1;" : "=f"(y) : "f"(x)); return y;
}
__device__ __forceinline__ float tanh_fast(float x) {
    float t = ex2f(x * 2.885390082f);
    return fmaf(-2.0f, rcpf(1.0f + t), 1.0f);
}
__device__ __forceinline__ float sigm_fast(float x) {
    float t = ex2f(x * -1.442695041f);
    return rcpf(1.0f + t);
}
__device__ __forceinline__ unsigned tanh_u2(unsigned x) {
    unsigned r;
    asm("tanh.approx.f16x2 %0, %1;" : "=r"(r) : "r"(x));
    return r;
}
__device__ __forceinline__ __half2 u2h2(unsigned u) {
    __half2 h; *reinterpret_cast<unsigned*>(&h) = u; return h;
}
__device__ __forceinline__ unsigned h22u(__half2 h) {
    return *reinterpret_cast<unsigned*>(&h);
}
__device__ __forceinline__ unsigned hadd2u(unsigned a, unsigned b) {
    return h22u(__hadd2(u2h2(a), u2h2(b)));
}

// ---------------------------------------------------------------------------
// K1: fused projections, tiled. keys emitted in half.
// ---------------------------------------------------------------------------
__global__ void __launch_bounds__(128) proj_kernel(
    const float* __restrict__ att, const float* __restrict__ W1,
    const float* __restrict__ b1,  __half* __restrict__ keys_h,
    const float* __restrict__ inp, const float* __restrict__ Wk,
    const float* __restrict__ lbias, float* __restrict__ xz)
{
    int bid = blockIdx.x;
    int j = threadIdx.x;
    if (bid < 256) {
        __shared__ float a_s[16][DATT];
        int row0 = bid * 16;
        for (int i = j; i < 16 * DATT; i += 128) {
            int r = i >> 7, d = i & 127;
            a_s[r][d] = att[(row0 + r) * DATT + d];
        }
        __syncthreads();
        float acc[16];
        float bj = b1[j];
        #pragma unroll
        for (int r = 0; r < 16; r++) acc[r] = bj;
        for (int l = 0; l < DATT; l++) {
            float wl = W1[l * LH + j];
            #pragma unroll
            for (int r = 0; r < 16; r++)
                acc[r] += a_s[r][l] * wl;
        }
        #pragma unroll
        for (int r = 0; r < 16; r++)
            keys_h[(row0 + r) * LH + j] = __float2half(acc[r]);
    } else {
        __shared__ float a_s[8][DIN];
        int row0 = (bid - 256) * 8;
        for (int i = j; i < 8 * DIN; i += 128) {
            int r = i >> 7, d = i & 127;
            a_s[r][d] = inp[(row0 + r) * DIN + d];
        }
        __syncthreads();
        float acc[4][8];
        #pragma unroll
        for (int c = 0; c < 4; c++) {
            float bc = lbias[j + c * 128];
            #pragma unroll
            for (int r = 0; r < 8; r++) acc[c][r] = bc;
        }
        for (int d = 0; d < DIN; d++) {
            float w0 = Wk[d * G4 + j];
            float w1 = Wk[d * G4 + j + 128];
            float w2 = Wk[d * G4 + j + 256];
            float w3 = Wk[d * G4 + j + 384];
            #pragma unroll
            for (int r = 0; r < 8; r++) {
                float av = a_s[r][d];
                acc[0][r] += av * w0;
                acc[1][r] += av * w1;
                acc[2][r] += av * w2;
                acc[3][r] += av * w3;
            }
        }
        #pragma unroll
        for (int r = 0; r < 8; r++) {
            float* o = xz + (row0 + r) * G4;
            o[j] = acc[0][r]; o[j + 128] = acc[1][r];
            o[j + 256] = acc[2][r]; o[j + 384] = acc[3][r];
        }
    }
}

// ---------------------------------------------------------------------------
// K2: LSTM scan — ALL weights in registers (48 f32 rows + 80 f16 rows as
//     40 half2). Zero weight smem traffic; h broadcast in f32 and half.
//     f16 partial sums in chains of 8 HFMA2, promoted to f32 (score-proven).
// ---------------------------------------------------------------------------
__global__ void __launch_bounds__(512, 1) lstm_kernel(
    const float* __restrict__ xz, const float* __restrict__ Wr,
    float* __restrict__ out)
{
    int b = blockIdx.x;
    int j = threadIdx.x;
    __shared__ __align__(16) float  h_f[LH];
    __shared__ __align__(16) __half h_h[LH];
    __shared__ float z_s[G4];

    // weights rows 0..47 as f32
    float wf[KF32];
    #pragma unroll
    for (int k = 0; k < KF32; k++)
        wf[k] = Wr[k * G4 + j];
    // weights rows 48..127 as half2 pairs (rows 48+2p, 49+2p)
    unsigned wh[KH16 / 2];
    #pragma unroll
    for (int p = 0; p < KH16 / 2; p++) {
        __half2 v = __floats2half2_rn(Wr[(KF32 + 2 * p) * G4 + j],
                                      Wr[(KF32 + 2 * p + 1) * G4 + j]);
        wh[p] = h22u(v);
    }

    if (j < LH) {
        h_f[j] = 0.0f;
        h_h[j] = __float2half(0.0f);
    }
    float c = 0.0f;
    __syncthreads();

    const float* xzb = xz + b * TOUT * G4;
    float xnext = xzb[j];
    bool is_g = (j >= 2 * LH) && (j < 3 * LH);

    for (int t = 0; t < TOUT; t++) {
        float acc0 = xnext;
        float acc1 = 0.0f;
        if (t + 1 < TOUT) xnext = xzb[(t + 1) * G4 + j];

        // f32 part: rows 0..47 (broadcast float4 h loads)
        #pragma unroll
        for (int kk = 0; kk < KF32 / 4; kk++) {
            float4 h4 = *reinterpret_cast<const float4*>(&h_f[kk * 4]);
            acc0 += h4.x * wf[kk * 4 + 0];
            acc1 += h4.y * wf[kk * 4 + 1];
            acc0 += h4.z * wf[kk * 4 + 2];
            acc1 += h4.w * wf[kk * 4 + 3];
        }
        // f16 part: rows 48..127, 5 chains of 8 HFMA2 (16 rows/chain),
        // each chain promoted to f32.
        const unsigned* hh = reinterpret_cast<const unsigned*>(&h_h[KF32]);
        #pragma unroll
        for (int ch = 0; ch < 5; ch++) {
            __half2 a = __floats2half2_rn(0.f, 0.f);
            #pragma unroll
            for (int i = 0; i < 8; i++) {
                int p = ch * 8 + i;
                a = __hfma2(u2h2(hh[p]), u2h2(wh[p]), a);
            }
            float2 f = __half22float2(a);
            acc0 += f.x;
            acc1 += f.y;
        }
        float z = acc0 + acc1;
        z_s[j] = is_g ? tanh_fast(z) : sigm_fast(z);
        __syncthreads();
        if (j < LH) {
            c = z_s[LH + j] * c + z_s[j] * z_s[2 * LH + j];
            float h = z_s[3 * LH + j] * tanh_fast(c);
            h_f[j] = h;
            h_h[j] = __float2half(h);
            out[(b * TOUT + t) * (LH + DATT) + j] = h;
        }
        __syncthreads();
    }
    if (j < LH) {
        out[OUT_H_OFF + b * LH + j] = h_f[j];
        out[OUT_C_OFF + b * LH + j] = c;
    }
}

// ---------------------------------------------------------------------------
// K3: q = x @ W2 + b2 -> half, tiled.
// ---------------------------------------------------------------------------
__global__ void __launch_bounds__(128) q_kernel(
    const float* __restrict__ out, const float* __restrict__ W2,
    const float* __restrict__ b2, __half* __restrict__ q_h)
{
    int row0 = blockIdx.x * 16;
    int j = threadIdx.x;
    __shared__ float x_s[16][LH];
    for (int i = j; i < 16 * LH; i += 128) {
        int r = i >> 7, l = i & 127;
        x_s[r][l] = out[(row0 + r) * (LH + DATT) + l];
    }
    __syncthreads();
    float acc[16];
    float bj = b2[j];
    #pragma unroll
    for (int r = 0; r < 16; r++) acc[r] = bj;
    for (int l = 0; l < LH; l++) {
        float wl = W2[l * LH + j];
        #pragma unroll
        for (int r = 0; r < 16; r++)
            acc[r] += x_s[r][l] * wl;
    }
    #pragma unroll
    for (int r = 0; r < 16; r++)
        q_h[(row0 + r) * LH + j] = __float2half(acc[r]);
}

// ---------------------------------------------------------------------------
// K4: raw scores (R6 proven).
// ---------------------------------------------------------------------------
__global__ void __launch_bounds__(256, 4) score_kernel(
    const __half* __restrict__ keys_h_g, const __half* __restrict__ q_h_g,
    const float* __restrict__ W3, float* __restrict__ sc_g)
{
    extern __shared__ char sm[];
    uint4*    keyv = reinterpret_cast<uint4*>(sm);
    uint4*    qv   = reinterpret_cast<uint4*>(sm + S_KEYS_SZ);
    uint4*    w3v  = reinterpret_cast<uint4*>(sm + S_KEYS_SZ + S_Q_SZ);
    unsigned* w3w  = reinterpret_cast<unsigned*>(sm + S_KEYS_SZ + S_Q_SZ);

    int b  = blockIdx.z;
    int q0 = blockIdx.y * 8;
    int k0 = blockIdx.x * 128;
    int tid = threadIdx.x;

    const uint4* kg = reinterpret_cast<const uint4*>(keys_h_g + (b * TIN + k0) * LH);
    for (int i = tid; i < 128 * 16; i += 256) {
        int k = i >> 4, cc = i & 15;
        keyv[k * KP4 + cc] = kg[k * 16 + cc];
    }
    if (tid < 128) {
        int r = tid >> 4, cc = tid & 15;
        qv[r * 16 + cc] = reinterpret_cast<const uint4*>(
            q_h_g + (b * TOUT + q0 + r) * LH)[cc];
    }
    if (tid < 64) {
        float2 v = *reinterpret_cast<const float2*>(&W3[2 * tid]);
        __half2 h = __floats2half2_rn(v.x, v.y);
        w3w[tid] = h22u(h);
    }
    __syncthreads();

    int ql = tid >> 5;
    int kk = tid & 31;
    const uint4* qrow = qv + ql * 16;

    float f0 = 0.f, f1 = 0.f, f2 = 0.f, f3 = 0.f;
    #pragma unroll
    for (int g2 = 0; g2 < 8; g2++) {
        __half2 z = __floats2half2_rn(0.f, 0.f);
        __half2 a0 = z, a1 = z, a2 = z, a3 = z;
        #pragma unroll
        for (int gg = 0; gg < 2; gg++) {
            int g = g2 * 2 + gg;
            uint4 q4 = qrow[g];
            uint4 w4 = w3v[g];
            uint4 kA = keyv[kk * KP4 + g];
            uint4 kB = keyv[(kk + 32) * KP4 + g];
            uint4 kC = keyv[(kk + 64) * KP4 + g];
            uint4 kD = keyv[(kk + 96) * KP4 + g];
            a0 = __hfma2(u2h2(tanh_u2(hadd2u(kA.x, q4.x))), u2h2(w4.x), a0);
            a1 = __hfma2(u2h2(tanh_u2(hadd2u(kB.x, q4.x))), u2h2(w4.x), a1);
            a2 = __hfma2(u2h2(tanh_u2(hadd2u(kC.x, q4.x))), u2h2(w4.x), a2);
            a3 = __hfma2(u2h2(tanh_u2(hadd2u(kD.x, q4.x))), u2h2(w4.x), a3);
            a0 = __hfma2(u2h2(tanh_u2(hadd2u(kA.y, q4.y))), u2h2(w4.y), a0);
            a1 = __hfma2(u2h2(tanh_u2(hadd2u(kB.y, q4.y))), u2h2(w4.y), a1);
            a2 = __hfma2(u2h2(tanh_u2(hadd2u(kC.y, q4.y))), u2h2(w4.y), a2);
            a3 = __hfma2(u2h2(tanh_u2(hadd2u(kD.y, q4.y))), u2h2(w4.y), a3);
            a0 = __hfma2(u2h2(tanh_u2(hadd2u(kA.z, q4.z))), u2h2(w4.z), a0);
            a1 = __hfma2(u2h2(tanh_u2(hadd2u(kB.z, q4.z))), u2h2(w4.z), a1);
            a2 = __hfma2(u2h2(tanh_u2(hadd2u(kC.z, q4.z))), u2h2(w4.z), a2);
            a3 = __hfma2(u2h2(tanh_u2(hadd2u(kD.z, q4.z))), u2h2(w4.z), a3);
            a0 = __hfma2(u2h2(tanh_u2(hadd2u(kA.w, q4.w))), u2h2(w4.w), a0);
            a1 = __hfma2(u2h2(tanh_u2(hadd2u(kB.w, q4.w))), u2h2(w4.w), a1);
            a2 = __hfma2(u2h2(tanh_u2(hadd2u(kC.w, q4.w))), u2h2(w4.w), a2);
            a3 = __hfma2(u2h2(tanh_u2(hadd2u(kD.w, q4.w))), u2h2(w4.w), a3);
        }
        float2 t0 = __half22float2(a0); f0 += t0.x + t0.y;
        float2 t1 = __half22float2(a1); f1 += t1.x + t1.y;
        float2 t2 = __half22float2(a2); f2 += t2.x + t2.y;
        float2 t3 = __half22float2(a3); f3 += t3.x + t3.y;
    }
    float* orow = sc_g + (b * TOUT + q0 + ql) * TIN + k0;
    orow[kk]      = f0;
    orow[kk + 32] = f1;
    orow[kk + 64] = f2;
    orow[kk + 96] = f3;
}

// ---------------------------------------------------------------------------
// K5: fused softmax + weighted (proven).
// ---------------------------------------------------------------------------
__global__ void __launch_bounds__(256) weighted_kernel(
    const float* __restrict__ sc_g, const float* __restrict__ att,
    float* __restrict__ out)
{
    int b  = blockIdx.y;
    int q0 = blockIdx.x * 16;
    int tid = threadIdx.x;

    __shared__ float a_s[16][TIN];
    for (int i = tid; i < 16 * TIN; i += 256) {
        int r = i >> 9, kk = i & 511;
        a_s[r][kk] = sc_g[(b * TOUT + q0 + r) * TIN + kk];
    }
    __syncthreads();

    int w = tid >> 5, lane = tid & 31;
    for (int r = w; r < 16; r += 8) {
        float* row = a_s[r];
        float v[16], mx = -1e30f;
        #pragma unroll
        for (int i = 0; i < 16; i++) {
            v[i] = row[lane + 32 * i];
            mx = fmaxf(mx, v[i]);
        }
        #pragma unroll
        for (int off = 16; off >= 1; off >>= 1)
            mx = fmaxf(mx, __shfl_xor_sync(0xffffffffu, mx, off));
        float s = 0.0f;
        #pragma unroll
        for (int i = 0; i < 16; i++) {
            v[i] = ex2f((v[i] - mx) * 1.442695041f);
            s += v[i];
        }
        #pragma unroll
        for (int off = 16; off >= 1; off >>= 1)
            s += __shfl_xor_sync(0xffffffffu, s, off);
        float inv = rcpf(s);
        #pragma unroll
        for (int i = 0; i < 16; i++)
            row[lane + 32 * i] = v[i] * inv;
    }
    __syncthreads();

    int d = tid & 127;
    int g = tid >> 7;
    float acc[8];
    #pragma unroll
    for (int i = 0; i < 8; i++) acc[i] = 0.0f;

    const float* ap = att + b * TIN * DATT + d;
    #pragma unroll 4
    for (int k = 0; k < TIN; k++) {
        float av = ap[k * DATT];
        #pragma unroll
        for (int i = 0; i < 8; i++)
            acc[i] += a_s[g * 8 + i][k] * av;
    }
    #pragma unroll
    for (int i = 0; i < 8; i++)
        out[(b * TOUT + q0 + g * 8 + i) * (LH + DATT) + LH + d] = acc[i];
}

// ---------------------------------------------------------------------------
extern "C" void kernel_launch(void* const* d_in, const int* in_sizes, int n_in,
                              void* d_out, int out_size)
{
    const float* inputs   = (const float*)d_in[0];
    const float* attended = (const float*)d_in[1];
    const float* Wk       = (const float*)d_in[2];
    const float* Wr       = (const float*)d_in[3];
    const float* lbias    = (const float*)d_in[4];
    const float* W1       = (const float*)d_in[5];
    const float* b1       = (const float*)d_in[6];
    const float* W2       = (const float*)d_in[7];
    const float* b2       = (const float*)d_in[8];
    const float* W3       = (const float*)d_in[9];
    float* out = (float*)d_out;

    cudaFuncSetAttribute(score_kernel,
                         cudaFuncAttributeMaxDynamicSharedMemorySize, SCORE_DSMEM);

    proj_kernel<<<512, 128>>>(attended, W1, b1, g_keys_h,
                              inputs, Wk, lbias, g_xz);
    lstm_kernel<<<NB, 512>>>(g_xz, Wr, out);
    q_kernel<<<NB * TOUT / 16, 128>>>(out, W2, b2, g_q_h);
    {
        dim3 grid(TIN / 128, TOUT / 8, NB);
        score_kernel<<<grid, 256, SCORE_DSMEM>>>(g_keys_h, g_q_h, W3, g_sc);
    }
    {
        dim3 grid(16, NB);
        weighted_kernel<<<grid, 256>>>(g_sc, attended, out);
    }
    (void)in_sizes; (void)n_in; (void)out_size;
}